// round 1
// baseline (speedup 1.0000x reference)
#include <cuda_runtime.h>

#define NT   8192
#define DIM  256
#define XLD  259          // X row stride (256 features + 3 position dims)
#define BM   64           // query rows per CTA
#define BN   64           // key cols per tile
#define KLD  260          // padded k-stride (floats) for Qs/Ks: mult of 4 (16B align), %32==4 (conflict-light)
#define PS_LD 68          // padded stride for probability tile

__device__ float g_Q[NT * DIM];
__device__ float g_K[NT * DIM];
__device__ float g_V[NT * DIM];

__device__ __forceinline__ float f4get(float4 v, int c) {
    return (c == 0) ? v.x : (c == 1) ? v.y : (c == 2) ? v.z : v.w;
}

// ---------------------------------------------------------------------------
// QKV GEMM: C[m][n] = sum_k Xf[m][k] * W[k][n] + b[n]
// grid = (128, 4, 3), 256 threads, 64x64 tile, 4x4 per thread
// ---------------------------------------------------------------------------
__global__ __launch_bounds__(256)
void qkv_kernel(const float* __restrict__ X,
                const float* __restrict__ WQ, const float* __restrict__ bQ,
                const float* __restrict__ WK, const float* __restrict__ bK,
                const float* __restrict__ WV, const float* __restrict__ bV)
{
    const float* W; const float* bias; float* C;
    if (blockIdx.z == 0)      { W = WQ; bias = bQ; C = g_Q; }
    else if (blockIdx.z == 1) { W = WK; bias = bK; C = g_K; }
    else                      { W = WV; bias = bV; C = g_V; }

    __shared__ float Xs[64][68];   // [m][k], padded
    __shared__ float Ws[64][64];   // [k][n]

    const int tid = threadIdx.x;
    const int ty = tid >> 4;       // 0..15 -> rows ty*4..+3
    const int tx = tid & 15;       // 0..15 -> cols tx + 16*j
    const int m0 = blockIdx.x * 64;
    const int n0 = blockIdx.y * 64;

    float acc[4][4] = {};

    for (int k0 = 0; k0 < DIM; k0 += 64) {
        // X tile: scalar loads (X rows are 259 floats -> not 16B aligned)
        #pragma unroll
        for (int i = 0; i < 16; i++) {
            int idx = tid + i * 256;
            int r = idx >> 6, c = idx & 63;
            Xs[r][c] = X[(m0 + r) * XLD + (k0 + c)];
        }
        // W tile: float4, coalesced
        #pragma unroll
        for (int i = 0; i < 4; i++) {
            int idx = tid + i * 256;           // 0..1023
            int r = idx >> 4, c4 = (idx & 15) << 2;
            *(float4*)&Ws[r][c4] = *(const float4*)&W[(k0 + r) * DIM + (n0 + c4)];
        }
        __syncthreads();

        #pragma unroll 4
        for (int k = 0; k < 64; k += 4) {
            float4 xv[4];
            #pragma unroll
            for (int i = 0; i < 4; i++)
                xv[i] = *(const float4*)&Xs[ty * 4 + i][k];
            #pragma unroll
            for (int kk = 0; kk < 4; kk++) {
                float wv[4];
                #pragma unroll
                for (int j = 0; j < 4; j++)
                    wv[j] = Ws[k + kk][tx + 16 * j];
                #pragma unroll
                for (int i = 0; i < 4; i++) {
                    float xs = f4get(xv[i], kk);
                    #pragma unroll
                    for (int j = 0; j < 4; j++)
                        acc[i][j] += xs * wv[j];
                }
            }
        }
        __syncthreads();
    }

    #pragma unroll
    for (int j = 0; j < 4; j++) {
        float bv = bias[n0 + tx + 16 * j];
        #pragma unroll
        for (int i = 0; i < 4; i++)
            C[(m0 + ty * 4 + i) * DIM + (n0 + tx + 16 * j)] = acc[i][j] + bv;
    }
}

// ---------------------------------------------------------------------------
// Flash attention with spatial decay + softmax-one + residual.
// grid = 128 CTAs (one per 64-row Q block), 256 threads, 1 CTA/SM.
// Online recurrence: m,s,O running; final H = O / (1 + s)  (the "+1" uses the
// converged global row max, which matches exp(x-m)/(1+sum exp(x-m)) exactly).
// ---------------------------------------------------------------------------
__global__ __launch_bounds__(256, 1)
void attn_kernel(const float* __restrict__ X, float* __restrict__ out)
{
    extern __shared__ float sm[];
    float* Qs = sm;                    // [BM][KLD]
    float* Ks = Qs + BM * KLD;         // [BN][KLD]
    float* Vs = Ks + BN * KLD;         // [BN][DIM]
    float* Ps = Vs + BN * DIM;         // [BM][PS_LD]
    float* qp = Ps + BM * PS_LD;       // [4][BM]  px,py,pz,|p|^2
    float* kp = qp + 4 * BM;           // [4][BN]

    const int tid = threadIdx.x;
    const int ty = tid >> 4;           // rows ty*4..+3
    const int tx = tid & 15;           // S cols tx+16*j ; O cols tx*4 + 64*u
    const int m0 = blockIdx.x * BM;

    // Q tile (row-major, float4) + query positions
    #pragma unroll
    for (int i = 0; i < 16; i++) {
        int idx = tid + i * 256;       // 0..4095
        int r = idx >> 6, c4 = (idx & 63) << 2;
        *(float4*)&Qs[r * KLD + c4] = *(const float4*)&g_Q[(m0 + r) * DIM + c4];
    }
    if (tid < BM) {
        float px = X[(m0 + tid) * XLD + DIM + 0];
        float py = X[(m0 + tid) * XLD + DIM + 1];
        float pz = X[(m0 + tid) * XLD + DIM + 2];
        qp[0 * BM + tid] = px;
        qp[1 * BM + tid] = py;
        qp[2 * BM + tid] = pz;
        qp[3 * BM + tid] = px * px + py * py + pz * pz;
    }
    __syncthreads();

    float qx[4], qy[4], qz[4], qsq[4];
    #pragma unroll
    for (int i = 0; i < 4; i++) {
        int r = ty * 4 + i;
        qx[i] = qp[0 * BM + r]; qy[i] = qp[1 * BM + r];
        qz[i] = qp[2 * BM + r]; qsq[i] = qp[3 * BM + r];
    }

    float m_i[4], s_i[4];
    float O[4][4][4];                  // [row i][chunk u][col c] -> col = tx*4 + 64u + c
    #pragma unroll
    for (int i = 0; i < 4; i++) {
        m_i[i] = -1e30f; s_i[i] = 0.f;
        #pragma unroll
        for (int u = 0; u < 4; u++)
            #pragma unroll
            for (int c = 0; c < 4; c++) O[i][u][c] = 0.f;
    }

    for (int j0 = 0; j0 < NT; j0 += BN) {
        __syncthreads();   // previous PV reads done before overwriting tiles

        #pragma unroll
        for (int i = 0; i < 16; i++) {
            int idx = tid + i * 256;
            int r = idx >> 6, c4 = (idx & 63) << 2;
            *(float4*)&Ks[r * KLD + c4] = *(const float4*)&g_K[(j0 + r) * DIM + c4];
            *(float4*)&Vs[r * DIM + c4] = *(const float4*)&g_V[(j0 + r) * DIM + c4];
        }
        if (tid < BN) {
            float px = X[(j0 + tid) * XLD + DIM + 0];
            float py = X[(j0 + tid) * XLD + DIM + 1];
            float pz = X[(j0 + tid) * XLD + DIM + 2];
            kp[0 * BN + tid] = px;
            kp[1 * BN + tid] = py;
            kp[2 * BN + tid] = pz;
            kp[3 * BN + tid] = px * px + py * py + pz * pz;
        }
        __syncthreads();

        float kx[4], ky[4], kz[4], ksq[4];
        #pragma unroll
        for (int j = 0; j < 4; j++) {
            int c = tx + 16 * j;
            kx[j] = kp[0 * BN + c]; ky[j] = kp[1 * BN + c];
            kz[j] = kp[2 * BN + c]; ksq[j] = kp[3 * BN + c];
        }

        // ---- S = Q K^T (4x4 per thread over depth 256) ----
        float sacc[4][4] = {};
        #pragma unroll 4
        for (int k = 0; k < DIM; k += 4) {
            float4 qv[4], kv[4];
            #pragma unroll
            for (int i = 0; i < 4; i++)
                qv[i] = *(const float4*)&Qs[(ty * 4 + i) * KLD + k];
            #pragma unroll
            for (int j = 0; j < 4; j++)
                kv[j] = *(const float4*)&Ks[(tx + 16 * j) * KLD + k];
            #pragma unroll
            for (int i = 0; i < 4; i++)
                #pragma unroll
                for (int j = 0; j < 4; j++)
                    sacc[i][j] += qv[i].x * kv[j].x + qv[i].y * kv[j].y
                                + qv[i].z * kv[j].z + qv[i].w * kv[j].w;
        }

        // ---- decay, online softmax-one update ----
        #pragma unroll
        for (int i = 0; i < 4; i++) {
            float xv[4];
            #pragma unroll
            for (int j = 0; j < 4; j++) {
                float sc = sacc[i][j] * 0.0625f;                  // 1/sqrt(256)
                float d2 = qsq[i] + ksq[j]
                         - 2.f * (qx[i] * kx[j] + qy[i] * ky[j] + qz[i] * kz[j]);
                d2 = fmaxf(d2, 0.f);
                float dec = __expf(-0.5f * d2);                   // sigma = 1
                xv[j] = sc * dec;
            }
            float mx = fmaxf(fmaxf(xv[0], xv[1]), fmaxf(xv[2], xv[3]));
            #pragma unroll
            for (int off = 8; off >= 1; off >>= 1)
                mx = fmaxf(mx, __shfl_xor_sync(0xffffffffu, mx, off));
            float m_new = fmaxf(m_i[i], mx);
            float a = __expf(m_i[i] - m_new);                     // first iter: exp(-huge)=0
            m_i[i] = m_new;
            float rs = 0.f;
            #pragma unroll
            for (int j = 0; j < 4; j++) {
                float p = __expf(xv[j] - m_new);
                rs += p;
                Ps[(ty * 4 + i) * PS_LD + tx + 16 * j] = p;
            }
            s_i[i] = s_i[i] * a + rs;
            #pragma unroll
            for (int u = 0; u < 4; u++)
                #pragma unroll
                for (int c = 0; c < 4; c++) O[i][u][c] *= a;
        }
        __syncthreads();   // Ps visible to all

        // ---- O += P @ V (4 rows x 16 cols per thread, cols strided by 64) ----
        #pragma unroll 2
        for (int j = 0; j < BN; j += 4) {
            float4 pv[4];
            #pragma unroll
            for (int i = 0; i < 4; i++)
                pv[i] = *(const float4*)&Ps[(ty * 4 + i) * PS_LD + j];
            #pragma unroll
            for (int jj = 0; jj < 4; jj++) {
                float4 vv[4];
                #pragma unroll
                for (int u = 0; u < 4; u++)
                    vv[u] = *(const float4*)&Vs[(j + jj) * DIM + tx * 4 + u * 64];
                #pragma unroll
                for (int i = 0; i < 4; i++) {
                    float p = f4get(pv[i], jj);
                    #pragma unroll
                    for (int u = 0; u < 4; u++) {
                        O[i][u][0] += p * vv[u].x;
                        O[i][u][1] += p * vv[u].y;
                        O[i][u][2] += p * vv[u].z;
                        O[i][u][3] += p * vv[u].w;
                    }
                }
            }
        }
    }

    // ---- epilogue: H = O/(1+s) + Xf ----
    #pragma unroll
    for (int i = 0; i < 4; i++) {
        float s = s_i[i];
        #pragma unroll
        for (int off = 8; off >= 1; off >>= 1)
            s += __shfl_xor_sync(0xffffffffu, s, off);
        float inv = 1.f / (1.f + s);
        int gr = m0 + ty * 4 + i;
        #pragma unroll
        for (int u = 0; u < 4; u++) {
            int c0 = tx * 4 + u * 64;
            float4 o;
            o.x = O[i][u][0] * inv + X[gr * XLD + c0 + 0];
            o.y = O[i][u][1] * inv + X[gr * XLD + c0 + 1];
            o.z = O[i][u][2] * inv + X[gr * XLD + c0 + 2];
            o.w = O[i][u][3] * inv + X[gr * XLD + c0 + 3];
            *(float4*)&out[gr * DIM + c0] = o;
        }
    }
}

#define ATTN_SMEM ((BM * KLD + BN * KLD + BN * DIM + BM * PS_LD + 8 * BM) * (int)sizeof(float))

extern "C" void kernel_launch(void* const* d_in, const int* in_sizes, int n_in,
                              void* d_out, int out_size)
{
    const float* X  = (const float*)d_in[0];
    const float* WQ = (const float*)d_in[1];
    const float* bQ = (const float*)d_in[2];
    const float* WK = (const float*)d_in[3];
    const float* bK = (const float*)d_in[4];
    const float* WV = (const float*)d_in[5];
    const float* bV = (const float*)d_in[6];
    float* out = (float*)d_out;

    // Not a stream op; idempotent; safe under graph capture.
    cudaFuncSetAttribute(attn_kernel, cudaFuncAttributeMaxDynamicSharedMemorySize, ATTN_SMEM);

    dim3 g1(NT / 64, DIM / 64, 3);
    qkv_kernel<<<g1, 256>>>(X, WQ, bQ, WK, bK, WV, bV);
    attn_kernel<<<NT / BM, 256, ATTN_SMEM>>>(X, out);
}

// round 3
// speedup vs baseline: 1.0001x; 1.0001x over previous
#include <cuda_runtime.h>

#define NT   8192
#define DIM  256
#define XLD  259          // X row stride (256 features + 3 position dims)
#define BM   64           // query rows per CTA
#define BN   64           // key cols per tile
#define KLD  260          // padded k-stride (floats) for Qs/Ks: mult of 4 (16B align), %32==4 (conflict-light)
#define PS_LD 68          // padded stride for probability tile

__device__ float g_Q[NT * DIM];
__device__ float g_K[NT * DIM];
__device__ float g_V[NT * DIM];

__device__ __forceinline__ float f4get(float4 v, int c) {
    return (c == 0) ? v.x : (c == 1) ? v.y : (c == 2) ? v.z : v.w;
}

// ---------------------------------------------------------------------------
// QKV GEMM: C[m][n] = sum_k Xf[m][k] * W[k][n] + b[n]
// grid = (128, 4, 3), 256 threads, 64x64 tile, 4x4 per thread
// ---------------------------------------------------------------------------
__global__ __launch_bounds__(256)
void qkv_kernel(const float* __restrict__ X,
                const float* __restrict__ WQ, const float* __restrict__ bQ,
                const float* __restrict__ WK, const float* __restrict__ bK,
                const float* __restrict__ WV, const float* __restrict__ bV)
{
    const float* W; const float* bias; float* C;
    if (blockIdx.z == 0)      { W = WQ; bias = bQ; C = g_Q; }
    else if (blockIdx.z == 1) { W = WK; bias = bK; C = g_K; }
    else                      { W = WV; bias = bV; C = g_V; }

    __shared__ float Xs[64][68];   // [m][k], padded
    __shared__ float Ws[64][64];   // [k][n]

    const int tid = threadIdx.x;
    const int ty = tid >> 4;       // 0..15 -> rows ty*4..+3
    const int tx = tid & 15;       // 0..15 -> cols tx + 16*j
    const int m0 = blockIdx.x * 64;
    const int n0 = blockIdx.y * 64;

    float acc[4][4] = {};

    for (int k0 = 0; k0 < DIM; k0 += 64) {
        // X tile: scalar loads (X rows are 259 floats -> not 16B aligned)
        #pragma unroll
        for (int i = 0; i < 16; i++) {
            int idx = tid + i * 256;
            int r = idx >> 6, c = idx & 63;
            Xs[r][c] = X[(m0 + r) * XLD + (k0 + c)];
        }
        // W tile: float4, coalesced
        #pragma unroll
        for (int i = 0; i < 4; i++) {
            int idx = tid + i * 256;           // 0..1023
            int r = idx >> 4, c4 = (idx & 15) << 2;
            *(float4*)&Ws[r][c4] = *(const float4*)&W[(k0 + r) * DIM + (n0 + c4)];
        }
        __syncthreads();

        #pragma unroll 4
        for (int k = 0; k < 64; k += 4) {
            float4 xv[4];
            #pragma unroll
            for (int i = 0; i < 4; i++)
                xv[i] = *(const float4*)&Xs[ty * 4 + i][k];
            #pragma unroll
            for (int kk = 0; kk < 4; kk++) {
                float wv[4];
                #pragma unroll
                for (int j = 0; j < 4; j++)
                    wv[j] = Ws[k + kk][tx + 16 * j];
                #pragma unroll
                for (int i = 0; i < 4; i++) {
                    float xs = f4get(xv[i], kk);
                    #pragma unroll
                    for (int j = 0; j < 4; j++)
                        acc[i][j] += xs * wv[j];
                }
            }
        }
        __syncthreads();
    }

    #pragma unroll
    for (int j = 0; j < 4; j++) {
        float bv = bias[n0 + tx + 16 * j];
        #pragma unroll
        for (int i = 0; i < 4; i++)
            C[(m0 + ty * 4 + i) * DIM + (n0 + tx + 16 * j)] = acc[i][j] + bv;
    }
}

// ---------------------------------------------------------------------------
// Flash attention with spatial decay + softmax-one + residual.
// grid = 128 CTAs (one per 64-row Q block), 256 threads, 1 CTA/SM.
// Online recurrence: m,s,O running; final H = O / (1 + s)  (the "+1" uses the
// converged global row max, which matches exp(x-m)/(1+sum exp(x-m)) exactly).
// ---------------------------------------------------------------------------
__global__ __launch_bounds__(256, 1)
void attn_kernel(const float* __restrict__ X, float* __restrict__ out)
{
    extern __shared__ float sm[];
    float* Qs = sm;                    // [BM][KLD]
    float* Ks = Qs + BM * KLD;         // [BN][KLD]
    float* Vs = Ks + BN * KLD;         // [BN][DIM]
    float* Ps = Vs + BN * DIM;         // [BM][PS_LD]
    float* qp = Ps + BM * PS_LD;       // [4][BM]  px,py,pz,|p|^2
    float* kp = qp + 4 * BM;           // [4][BN]

    const int tid = threadIdx.x;
    const int ty = tid >> 4;           // rows ty*4..+3
    const int tx = tid & 15;           // S cols tx+16*j ; O cols tx*4 + 64*u
    const int m0 = blockIdx.x * BM;

    // Q tile (row-major, float4) + query positions
    #pragma unroll
    for (int i = 0; i < 16; i++) {
        int idx = tid + i * 256;       // 0..4095
        int r = idx >> 6, c4 = (idx & 63) << 2;
        *(float4*)&Qs[r * KLD + c4] = *(const float4*)&g_Q[(m0 + r) * DIM + c4];
    }
    if (tid < BM) {
        float px = X[(m0 + tid) * XLD + DIM + 0];
        float py = X[(m0 + tid) * XLD + DIM + 1];
        float pz = X[(m0 + tid) * XLD + DIM + 2];
        qp[0 * BM + tid] = px;
        qp[1 * BM + tid] = py;
        qp[2 * BM + tid] = pz;
        qp[3 * BM + tid] = px * px + py * py + pz * pz;
    }
    __syncthreads();

    float qx[4], qy[4], qz[4], qsq[4];
    #pragma unroll
    for (int i = 0; i < 4; i++) {
        int r = ty * 4 + i;
        qx[i] = qp[0 * BM + r]; qy[i] = qp[1 * BM + r];
        qz[i] = qp[2 * BM + r]; qsq[i] = qp[3 * BM + r];
    }

    float m_i[4], s_i[4];
    float O[4][4][4];                  // [row i][chunk u][col c] -> col = tx*4 + 64u + c
    #pragma unroll
    for (int i = 0; i < 4; i++) {
        m_i[i] = -1e30f; s_i[i] = 0.f;
        #pragma unroll
        for (int u = 0; u < 4; u++)
            #pragma unroll
            for (int c = 0; c < 4; c++) O[i][u][c] = 0.f;
    }

    for (int j0 = 0; j0 < NT; j0 += BN) {
        __syncthreads();   // previous PV reads done before overwriting tiles

        #pragma unroll
        for (int i = 0; i < 16; i++) {
            int idx = tid + i * 256;
            int r = idx >> 6, c4 = (idx & 63) << 2;
            *(float4*)&Ks[r * KLD + c4] = *(const float4*)&g_K[(j0 + r) * DIM + c4];
            *(float4*)&Vs[r * DIM + c4] = *(const float4*)&g_V[(j0 + r) * DIM + c4];
        }
        if (tid < BN) {
            float px = X[(j0 + tid) * XLD + DIM + 0];
            float py = X[(j0 + tid) * XLD + DIM + 1];
            float pz = X[(j0 + tid) * XLD + DIM + 2];
            kp[0 * BN + tid] = px;
            kp[1 * BN + tid] = py;
            kp[2 * BN + tid] = pz;
            kp[3 * BN + tid] = px * px + py * py + pz * pz;
        }
        __syncthreads();

        float kx[4], ky[4], kz[4], ksq[4];
        #pragma unroll
        for (int j = 0; j < 4; j++) {
            int c = tx + 16 * j;
            kx[j] = kp[0 * BN + c]; ky[j] = kp[1 * BN + c];
            kz[j] = kp[2 * BN + c]; ksq[j] = kp[3 * BN + c];
        }

        // ---- S = Q K^T (4x4 per thread over depth 256) ----
        float sacc[4][4] = {};
        #pragma unroll 4
        for (int k = 0; k < DIM; k += 4) {
            float4 qv[4], kv[4];
            #pragma unroll
            for (int i = 0; i < 4; i++)
                qv[i] = *(const float4*)&Qs[(ty * 4 + i) * KLD + k];
            #pragma unroll
            for (int j = 0; j < 4; j++)
                kv[j] = *(const float4*)&Ks[(tx + 16 * j) * KLD + k];
            #pragma unroll
            for (int i = 0; i < 4; i++)
                #pragma unroll
                for (int j = 0; j < 4; j++)
                    sacc[i][j] += qv[i].x * kv[j].x + qv[i].y * kv[j].y
                                + qv[i].z * kv[j].z + qv[i].w * kv[j].w;
        }

        // ---- decay, online softmax-one update ----
        #pragma unroll
        for (int i = 0; i < 4; i++) {
            float xv[4];
            #pragma unroll
            for (int j = 0; j < 4; j++) {
                float sc = sacc[i][j] * 0.0625f;                  // 1/sqrt(256)
                float d2 = qsq[i] + ksq[j]
                         - 2.f * (qx[i] * kx[j] + qy[i] * ky[j] + qz[i] * kz[j]);
                d2 = fmaxf(d2, 0.f);
                float dec = __expf(-0.5f * d2);                   // sigma = 1
                xv[j] = sc * dec;
            }
            float mx = fmaxf(fmaxf(xv[0], xv[1]), fmaxf(xv[2], xv[3]));
            #pragma unroll
            for (int off = 8; off >= 1; off >>= 1)
                mx = fmaxf(mx, __shfl_xor_sync(0xffffffffu, mx, off));
            float m_new = fmaxf(m_i[i], mx);
            float a = __expf(m_i[i] - m_new);                     // first iter: exp(-huge)=0
            m_i[i] = m_new;
            float rs = 0.f;
            #pragma unroll
            for (int j = 0; j < 4; j++) {
                float p = __expf(xv[j] - m_new);
                rs += p;
                Ps[(ty * 4 + i) * PS_LD + tx + 16 * j] = p;
            }
            s_i[i] = s_i[i] * a + rs;
            #pragma unroll
            for (int u = 0; u < 4; u++)
                #pragma unroll
                for (int c = 0; c < 4; c++) O[i][u][c] *= a;
        }
        __syncthreads();   // Ps visible to all

        // ---- O += P @ V (4 rows x 16 cols per thread, cols strided by 64) ----
        #pragma unroll 2
        for (int j = 0; j < BN; j += 4) {
            float4 pv[4];
            #pragma unroll
            for (int i = 0; i < 4; i++)
                pv[i] = *(const float4*)&Ps[(ty * 4 + i) * PS_LD + j];
            #pragma unroll
            for (int jj = 0; jj < 4; jj++) {
                float4 vv[4];
                #pragma unroll
                for (int u = 0; u < 4; u++)
                    vv[u] = *(const float4*)&Vs[(j + jj) * DIM + tx * 4 + u * 64];
                #pragma unroll
                for (int i = 0; i < 4; i++) {
                    float p = f4get(pv[i], jj);
                    #pragma unroll
                    for (int u = 0; u < 4; u++) {
                        O[i][u][0] += p * vv[u].x;
                        O[i][u][1] += p * vv[u].y;
                        O[i][u][2] += p * vv[u].z;
                        O[i][u][3] += p * vv[u].w;
                    }
                }
            }
        }
    }

    // ---- epilogue: H = O/(1+s) + Xf ----
    #pragma unroll
    for (int i = 0; i < 4; i++) {
        float s = s_i[i];
        #pragma unroll
        for (int off = 8; off >= 1; off >>= 1)
            s += __shfl_xor_sync(0xffffffffu, s, off);
        float inv = 1.f / (1.f + s);
        int gr = m0 + ty * 4 + i;
        #pragma unroll
        for (int u = 0; u < 4; u++) {
            int c0 = tx * 4 + u * 64;
            float4 o;
            o.x = O[i][u][0] * inv + X[gr * XLD + c0 + 0];
            o.y = O[i][u][1] * inv + X[gr * XLD + c0 + 1];
            o.z = O[i][u][2] * inv + X[gr * XLD + c0 + 2];
            o.w = O[i][u][3] * inv + X[gr * XLD + c0 + 3];
            *(float4*)&out[gr * DIM + c0] = o;
        }
    }
}

#define ATTN_SMEM ((BM * KLD + BN * KLD + BN * DIM + BM * PS_LD + 8 * BM) * (int)sizeof(float))

extern "C" void kernel_launch(void* const* d_in, const int* in_sizes, int n_in,
                              void* d_out, int out_size)
{
    const float* X  = (const float*)d_in[0];
    const float* WQ = (const float*)d_in[1];
    const float* bQ = (const float*)d_in[2];
    const float* WK = (const float*)d_in[3];
    const float* bK = (const float*)d_in[4];
    const float* WV = (const float*)d_in[5];
    const float* bV = (const float*)d_in[6];
    float* out = (float*)d_out;

    // Not a stream op; idempotent; safe under graph capture.
    cudaFuncSetAttribute(attn_kernel, cudaFuncAttributeMaxDynamicSharedMemorySize, ATTN_SMEM);

    dim3 g1(NT / 64, DIM / 64, 3);
    qkv_kernel<<<g1, 256>>>(X, WQ, bQ, WK, bK, WV, bV);
    attn_kernel<<<NT / BM, 256, ATTN_SMEM>>>(X, out);
}

// round 10
// speedup vs baseline: 3.5999x; 3.5995x over previous
#include <cuda_runtime.h>
#include <cuda_bf16.h>
#include <cstdint>
#include <cstddef>

#define NT     8192
#define XLD    259
#define NTILES 64           // 4096 keys per CTA half / 64 per tile

// ---------------- device globals ----------------
__device__ __nv_bfloat16 g_Qb[NT * 256];
__device__ __nv_bfloat16 g_Kb[NT * 256];
__device__ __nv_bfloat16 g_Vt[256 * NT];     // V transposed: [dim][token]
__device__ float4        g_pos4[NT];         // px,py,pz,|p|^2
__device__ float         g_Opart[2 * NT * 256];
__device__ float         g_spart[2 * NT];
__device__ float         g_mpart[2 * NT];

// ---------------- PTX helpers (base ISA only: sm_80-class) ----------------
__device__ __forceinline__ uint32_t smem_u32(const void* p) {
    uint32_t a;
    asm("{ .reg .u64 t; cvta.to.shared.u64 t, %1; cvt.u32.u64 %0, t; }" : "=r"(a) : "l"(p));
    return a;
}
#define CP_COMMIT() asm volatile("cp.async.commit_group;" ::: "memory")
#define CP_WAIT0()  asm volatile("cp.async.wait_group 0;" ::: "memory")
#define CP_WAIT1()  asm volatile("cp.async.wait_group 1;" ::: "memory")
__device__ __forceinline__ void cp16(uint32_t dst, const void* src) {
    asm volatile("cp.async.cg.shared.global [%0], [%1], 16;" :: "r"(dst), "l"(src));
}
__device__ __forceinline__ void ldsm4(uint32_t addr, uint32_t& r0, uint32_t& r1, uint32_t& r2, uint32_t& r3) {
    asm volatile("ldmatrix.sync.aligned.m8n8.x4.shared.b16 {%0,%1,%2,%3}, [%4];"
        : "=r"(r0), "=r"(r1), "=r"(r2), "=r"(r3) : "r"(addr));
}
__device__ __forceinline__ void mma_bf16(float& c0, float& c1, float& c2, float& c3,
                                         uint32_t a0, uint32_t a1, uint32_t a2, uint32_t a3,
                                         uint32_t b0, uint32_t b1) {
    asm volatile("mma.sync.aligned.m16n8k16.row.col.f32.bf16.bf16.f32 "
        "{%0,%1,%2,%3}, {%4,%5,%6,%7}, {%8,%9}, {%0,%1,%2,%3};"
        : "+f"(c0), "+f"(c1), "+f"(c2), "+f"(c3)
        : "r"(a0), "r"(a1), "r"(a2), "r"(a3), "r"(b0), "r"(b1));
}
#define SWZ(x) ((x) ^ (((x) >> 3) & 0x70))

// ---------------- SMEM layout (attn) ----------------
// pos: 2 x 1KB | Q: 4 fb-blocks x 128 rows x 128B = 64KB | K: 2 x 32KB | V: 2 x 32KB
#define SM_POS  0
#define SM_Q    4096
#define SM_K    69632
#define SM_V    135168
#define ATTN_SMEM 200704

// ---------------------------------------------------------------------------
// QKV GEMM (SIMT fp32) -> bf16; V stored transposed.
// ---------------------------------------------------------------------------
__device__ __forceinline__ float f4get(float4 v, int c) {
    return (c == 0) ? v.x : (c == 1) ? v.y : (c == 2) ? v.z : v.w;
}

__global__ __launch_bounds__(256)
void qkv_kernel(const float* __restrict__ X,
                const float* __restrict__ WQ, const float* __restrict__ bQ,
                const float* __restrict__ WK, const float* __restrict__ bK,
                const float* __restrict__ WV, const float* __restrict__ bV)
{
    const float* W; const float* bias;
    if (blockIdx.z == 0)      { W = WQ; bias = bQ; }
    else if (blockIdx.z == 1) { W = WK; bias = bK; }
    else                      { W = WV; bias = bV; }

    __shared__ float Xs[64][68];
    __shared__ float Ws[64][64];

    const int tid = threadIdx.x;
    const int ty = tid >> 4, tx = tid & 15;
    const int m0 = blockIdx.x * 64, n0 = blockIdx.y * 64;

    float acc[4][4] = {};

    for (int k0 = 0; k0 < 256; k0 += 64) {
        #pragma unroll
        for (int i = 0; i < 16; i++) {
            int idx = tid + i * 256;
            int r = idx >> 6, c = idx & 63;
            Xs[r][c] = X[(m0 + r) * XLD + (k0 + c)];
        }
        #pragma unroll
        for (int i = 0; i < 4; i++) {
            int idx = tid + i * 256;
            int r = idx >> 4, c4 = (idx & 15) << 2;
            *(float4*)&Ws[r][c4] = *(const float4*)&W[(k0 + r) * 256 + (n0 + c4)];
        }
        __syncthreads();
        #pragma unroll 4
        for (int k = 0; k < 64; k += 4) {
            float4 xv[4];
            #pragma unroll
            for (int i = 0; i < 4; i++) xv[i] = *(const float4*)&Xs[ty * 4 + i][k];
            #pragma unroll
            for (int kk = 0; kk < 4; kk++) {
                float wv[4];
                #pragma unroll
                for (int j = 0; j < 4; j++) wv[j] = Ws[k + kk][tx + 16 * j];
                #pragma unroll
                for (int i = 0; i < 4; i++) {
                    float xs = f4get(xv[i], kk);
                    #pragma unroll
                    for (int j = 0; j < 4; j++) acc[i][j] += xs * wv[j];
                }
            }
        }
        __syncthreads();
    }

    if (blockIdx.z == 2) {
        #pragma unroll
        for (int j = 0; j < 4; j++) {
            int n = n0 + tx + 16 * j;
            float bv = bias[n];
            #pragma unroll
            for (int i = 0; i < 4; i++)
                g_Vt[(size_t)n * NT + (m0 + ty * 4 + i)] = __float2bfloat16_rn(acc[i][j] + bv);
        }
    } else {
        __nv_bfloat16* C = (blockIdx.z == 0) ? g_Qb : g_Kb;
        #pragma unroll
        for (int j = 0; j < 4; j++) {
            int n = n0 + tx + 16 * j;
            float bv = bias[n];
            #pragma unroll
            for (int i = 0; i < 4; i++)
                C[(size_t)(m0 + ty * 4 + i) * 256 + n] = __float2bfloat16_rn(acc[i][j] + bv);
        }
    }
}

__global__ void pos_kernel(const float* __restrict__ X)
{
    int i = blockIdx.x * 256 + threadIdx.x;
    float x = X[(size_t)i * XLD + 256];
    float y = X[(size_t)i * XLD + 257];
    float z = X[(size_t)i * XLD + 258];
    g_pos4[i] = make_float4(x, y, z, x * x + y * y + z * z);
}

// ---------------- tile loaders (cp.async, SW128-swizzled) ----------------
// K tile: [64 keys][256 feats] as 4 fb-blocks of [64 rows x 128B]
__device__ __forceinline__ void load_k(uint32_t sb, int tid, int j0, int buf) {
    uint32_t kb = sb + SM_K + (uint32_t)buf * 32768u;
    #pragma unroll
    for (int i = 0; i < 8; i++) {
        int e = i * 256 + tid;               // 0..2047
        int key = e >> 5, q = e & 31;
        int fb = q >> 3, f8 = q & 7;
        uint32_t off = (uint32_t)(fb * 8192 + SWZ(key * 128 + f8 * 16));
        cp16(kb + off, (const char*)g_Kb + (((size_t)(j0 + key)) * 256 + fb * 64 + f8 * 8) * 2);
    }
}
// V^T tile: [256 dims][64 keys], 128B rows
__device__ __forceinline__ void load_v(uint32_t sb, int tid, int j0, int buf) {
    uint32_t vb = sb + SM_V + (uint32_t)buf * 32768u;
    #pragma unroll
    for (int i = 0; i < 8; i++) {
        int e = i * 256 + tid;
        int dim = e >> 3, q = e & 7;
        uint32_t off = (uint32_t)SWZ(dim * 128 + q * 16);
        cp16(vb + off, (const char*)g_Vt + (((size_t)dim) * NT + j0 + q * 8) * 2);
    }
}
__device__ __forceinline__ void load_pos(uint32_t sb, int tid, int j0, int buf) {
    if (tid < 64) cp16(sb + SM_POS + (uint32_t)buf * 1024u + tid * 16u, &g_pos4[j0 + tid]);
}

__device__ __forceinline__ float softel(float s, float4 q, float4 k, float& rmx) {
    float dot = fmaf(q.z, k.z, fmaf(q.y, k.y, q.x * k.x));
    float d2 = fmaxf(fmaf(-2.f, dot, q.w + k.w), 0.f);
    float x = s * 0.0625f * __expf(-0.5f * d2);
    rmx = fmaxf(rmx, x);
    return __expf(x);
}

// ---------------------------------------------------------------------------
// HMMA flash attention. grid = 128: CTA = (q-block of 128 rows, KV half 4096).
// Unshifted exp: p=exp(x); m tracked as scalar max; O never rescaled.
// warp w owns rows 16w..16w+15; S C-frags feed P A-frags directly in regs.
// ---------------------------------------------------------------------------
__global__ __launch_bounds__(256, 1)
void attn_kernel()
{
    extern __shared__ char smem[];
    const uint32_t sb = smem_u32(smem);
    const int tid = threadIdx.x;
    const int w = tid >> 5, l = tid & 31;
    const int g = l >> 2, t = l & 3;
    const int qb = blockIdx.x >> 1, half = blockIdx.x & 1;
    const int m0 = qb * 128, j0b = half * 4096;

    // ---- Q -> smem (once), K/V/pos tile 0 ----
    #pragma unroll
    for (int i = 0; i < 16; i++) {
        int e = i * 256 + tid;               // 0..4095
        int row = e >> 5, q = e & 31;
        int fb = q >> 3, f8 = q & 7;
        uint32_t off = (uint32_t)(fb * 16384 + SWZ(row * 128 + f8 * 16));
        cp16(sb + SM_Q + off, (const char*)g_Qb + (((size_t)(m0 + row)) * 256 + fb * 64 + f8 * 8) * 2);
    }
    load_k(sb, tid, j0b, 0);
    load_v(sb, tid, j0b, 0);
    load_pos(sb, tid, j0b, 0);
    CP_COMMIT();

    const float4 qpa = g_pos4[m0 + 16 * w + g];        // row g
    const float4 qpb = g_pos4[m0 + 16 * w + g + 8];    // row g+8

    float O[32][4];
    #pragma unroll
    for (int n = 0; n < 32; n++) { O[n][0] = O[n][1] = O[n][2] = O[n][3] = 0.f; }
    float rmax0 = -1e30f, rmax1 = -1e30f, rsum0 = 0.f, rsum1 = 0.f;

    // ldmatrix lane address components (constant per thread)
    const int lrow16 = l & 15;                 // A-frag row within 16
    const int lkh    = l >> 4;                 // A-frag k-half
    const int lr8    = (l & 7) + (l >> 4) * 8; // B-frag row (key/dim within 16)
    const int lbh    = (l >> 3) & 1;           // B-frag k-half bit

    for (int tt = 0; tt < NTILES; tt++) {
        const int buf = tt & 1;
        if (tt < NTILES - 1) {
            load_k(sb, tid, j0b + (tt + 1) * 64, (tt + 1) & 1);
            load_v(sb, tid, j0b + (tt + 1) * 64, (tt + 1) & 1);
            load_pos(sb, tid, j0b + (tt + 1) * 64, (tt + 1) & 1);
            CP_COMMIT();
            CP_WAIT1();
        } else {
            CP_WAIT0();
        }
        __syncthreads();

        // ---- S = Q K^T : 8 n-tiles (64 keys), K-depth 256 ----
        float S[8][4];
        #pragma unroll
        for (int n = 0; n < 8; n++) { S[n][0] = S[n][1] = S[n][2] = S[n][3] = 0.f; }
        const uint32_t kbase = sb + SM_K + (uint32_t)buf * 32768u;

        #pragma unroll 4
        for (int ks = 0; ks < 16; ks++) {
            const int fb = ks >> 2, kc = (ks & 3) * 2;
            uint32_t a0, a1, a2, a3;
            ldsm4(sb + SM_Q + fb * 16384 + SWZ((16 * w + lrow16) * 128 + (kc + lkh) * 16),
                  a0, a1, a2, a3);
            #pragma unroll
            for (int jj = 0; jj < 4; jj++) {
                uint32_t b0, b1, b2, b3;
                ldsm4(kbase + fb * 8192 + SWZ((16 * jj + lr8) * 128 + (kc + lbh) * 16),
                      b0, b1, b2, b3);
                mma_bf16(S[2*jj][0], S[2*jj][1], S[2*jj][2], S[2*jj][3], a0, a1, a2, a3, b0, b1);
                mma_bf16(S[2*jj+1][0], S[2*jj+1][1], S[2*jj+1][2], S[2*jj+1][3], a0, a1, a2, a3, b2, b3);
            }
        }

        // ---- softmax + decay -> P (bf16 A-frags, in regs) ----
        uint32_t pk[8], pk2[8];
        const char* posb = smem + SM_POS + buf * 1024;
        #pragma unroll
        for (int nt = 0; nt < 8; nt++) {
            int c0 = 8 * nt + 2 * t;
            float4 k0 = *(const float4*)(posb + c0 * 16);
            float4 k1 = *(const float4*)(posb + c0 * 16 + 16);
            float p00 = softel(S[nt][0], qpa, k0, rmax0);
            float p01 = softel(S[nt][1], qpa, k1, rmax0);
            float p10 = softel(S[nt][2], qpb, k0, rmax1);
            float p11 = softel(S[nt][3], qpb, k1, rmax1);
            rsum0 += p00 + p01;
            rsum1 += p10 + p11;
            __nv_bfloat162 h0 = __floats2bfloat162_rn(p00, p01);
            __nv_bfloat162 h1 = __floats2bfloat162_rn(p10, p11);
            pk[nt]  = *(uint32_t*)&h0;
            pk2[nt] = *(uint32_t*)&h1;
        }

        // ---- O += P V : k = 64 keys (4 ksteps), n = 256 dims (32 tiles) ----
        const uint32_t vbase = sb + SM_V + (uint32_t)buf * 32768u;
        #pragma unroll
        for (int j2 = 0; j2 < 4; j2++) {
            uint32_t a0 = pk[2*j2], a1 = pk2[2*j2], a2 = pk[2*j2+1], a3 = pk2[2*j2+1];
            #pragma unroll
            for (int dd = 0; dd < 16; dd++) {
                uint32_t b0, b1, b2, b3;
                ldsm4(vbase + SWZ((16 * dd + lr8) * 128 + (2 * j2 + lbh) * 16),
                      b0, b1, b2, b3);
                mma_bf16(O[2*dd][0], O[2*dd][1], O[2*dd][2], O[2*dd][3], a0, a1, a2, a3, b0, b1);
                mma_bf16(O[2*dd+1][0], O[2*dd+1][1], O[2*dd+1][2], O[2*dd+1][3], a0, a1, a2, a3, b2, b3);
            }
        }
        __syncthreads();   // all warps done with buf before it is overwritten
    }

    // ---- complete row reductions across the quad (lanes sharing g) ----
    #pragma unroll
    for (int off = 1; off <= 2; off <<= 1) {
        rmax0 = fmaxf(rmax0, __shfl_xor_sync(0xffffffffu, rmax0, off));
        rmax1 = fmaxf(rmax1, __shfl_xor_sync(0xffffffffu, rmax1, off));
        rsum0 += __shfl_xor_sync(0xffffffffu, rsum0, off);
        rsum1 += __shfl_xor_sync(0xffffffffu, rsum1, off);
    }
    if (t == 0) {
        int r0 = m0 + 16 * w + g;
        g_mpart[half * NT + r0] = rmax0;
        g_mpart[half * NT + r0 + 8] = rmax1;
        g_spart[half * NT + r0] = rsum0;
        g_spart[half * NT + r0 + 8] = rsum1;
    }

    // ---- O writeback (fp32 partials) ----
    float* ob = &g_Opart[(size_t)half * NT * 256];
    const int row0 = m0 + 16 * w + g;
    #pragma unroll
    for (int nt = 0; nt < 32; nt++) {
        int col = 8 * nt + 2 * t;
        *(float2*)&ob[(size_t)row0 * 256 + col]       = make_float2(O[nt][0], O[nt][1]);
        *(float2*)&ob[(size_t)(row0 + 8) * 256 + col] = make_float2(O[nt][2], O[nt][3]);
    }
}

// ---------------------------------------------------------------------------
// merge: H = (O0+O1)/(exp(max(m0,m1)) + s0 + s1) + Xf
// ---------------------------------------------------------------------------
__global__ __launch_bounds__(256)
void merge_kernel(const float* __restrict__ X, float* __restrict__ out)
{
    int r = blockIdx.x * 4 + (threadIdx.x >> 6);
    int c = (threadIdx.x & 63) * 4;
    float m = fmaxf(g_mpart[r], g_mpart[NT + r]);
    float d = 1.f / (__expf(m) + g_spart[r] + g_spart[NT + r]);
    float4 o0 = *(const float4*)&g_Opart[(size_t)r * 256 + c];
    float4 o1 = *(const float4*)&g_Opart[(size_t)NT * 256 + (size_t)r * 256 + c];
    const float* xr = &X[(size_t)r * XLD + c];
    float4 o;
    o.x = (o0.x + o1.x) * d + xr[0];
    o.y = (o0.y + o1.y) * d + xr[1];
    o.z = (o0.z + o1.z) * d + xr[2];
    o.w = (o0.w + o1.w) * d + xr[3];
    *(float4*)&out[(size_t)r * 256 + c] = o;
}

extern "C" void kernel_launch(void* const* d_in, const int* in_sizes, int n_in,
                              void* d_out, int out_size)
{
    const float* X  = (const float*)d_in[0];
    const float* WQ = (const float*)d_in[1];
    const float* bQ = (const float*)d_in[2];
    const float* WK = (const float*)d_in[3];
    const float* bK = (const float*)d_in[4];
    const float* WV = (const float*)d_in[5];
    const float* bV = (const float*)d_in[6];
    float* out = (float*)d_out;

    cudaFuncSetAttribute(attn_kernel, cudaFuncAttributeMaxDynamicSharedMemorySize, ATTN_SMEM);

    pos_kernel<<<NT / 256, 256>>>(X);
    dim3 g1(NT / 64, 4, 3);
    qkv_kernel<<<g1, 256>>>(X, WQ, bQ, WK, bK, WV, bV);
    attn_kernel<<<128, 256, ATTN_SMEM>>>();
    merge_kernel<<<NT / 4, 256>>>(X, out);
}

// round 12
// speedup vs baseline: 5.5498x; 1.5417x over previous
#include <cuda_runtime.h>
#include <cuda_bf16.h>
#include <cstdint>
#include <cstddef>

#define NT     8192
#define XLD    259
#define NTILES 64           // 4096 keys per CTA half / 64 per tile

// ---------------- device globals ----------------
__device__ __nv_bfloat16 g_Qb[NT * 256];
__device__ __nv_bfloat16 g_Kb[NT * 256];
__device__ __nv_bfloat16 g_Vt[256 * NT];     // V transposed: [dim][token]
__device__ float4        g_pos4[NT];         // px,py,pz,|p|^2
__device__ float         g_Opart[2 * NT * 256];
__device__ float         g_spart[2 * NT];
__device__ float         g_mpart[2 * NT];

// ---------------- PTX helpers (base ISA only) ----------------
__device__ __forceinline__ uint32_t smem_u32(const void* p) {
    uint32_t a;
    asm("{ .reg .u64 t; cvta.to.shared.u64 t, %1; cvt.u32.u64 %0, t; }" : "=r"(a) : "l"(p));
    return a;
}
#define CP_COMMIT() asm volatile("cp.async.commit_group;" ::: "memory")
#define CP_WAIT0()  asm volatile("cp.async.wait_group 0;" ::: "memory")
#define CP_WAIT1()  asm volatile("cp.async.wait_group 1;" ::: "memory")
__device__ __forceinline__ void cp16(uint32_t dst, const void* src) {
    asm volatile("cp.async.cg.shared.global [%0], [%1], 16;" :: "r"(dst), "l"(src));
}
__device__ __forceinline__ void ldsm4(uint32_t addr, uint32_t& r0, uint32_t& r1, uint32_t& r2, uint32_t& r3) {
    asm volatile("ldmatrix.sync.aligned.m8n8.x4.shared.b16 {%0,%1,%2,%3}, [%4];"
        : "=r"(r0), "=r"(r1), "=r"(r2), "=r"(r3) : "r"(addr));
}
__device__ __forceinline__ void mma_bf16(float& c0, float& c1, float& c2, float& c3,
                                         uint32_t a0, uint32_t a1, uint32_t a2, uint32_t a3,
                                         uint32_t b0, uint32_t b1) {
    asm volatile("mma.sync.aligned.m16n8k16.row.col.f32.bf16.bf16.f32 "
        "{%0,%1,%2,%3}, {%4,%5,%6,%7}, {%8,%9}, {%0,%1,%2,%3};"
        : "+f"(c0), "+f"(c1), "+f"(c2), "+f"(c3)
        : "r"(a0), "r"(a1), "r"(a2), "r"(a3), "r"(b0), "r"(b1));
}
#define SWZ(x) ((x) ^ (((x) >> 3) & 0x70))

// ---------------- SMEM layout (attn) ----------------
#define SM_POS  0          // 2 x 1024
#define SM_P    2048       // 16384  (128 rows x 64 keys bf16, 128B rows)
#define SM_Q    18432      // 65536  (4 fb-blocks x 128 rows x 128B)
#define SM_K    83968      // 2 x 32768
#define SM_V    149504     // 2 x 32768
#define SM_RED  215040     // 2048: red_m[2][128], red_s[2][128]
#define ATTN_SMEM 217088

// ---------------------------------------------------------------------------
// QKV GEMM (SIMT fp32) -> bf16; V stored transposed.
// ---------------------------------------------------------------------------
__device__ __forceinline__ float f4get(float4 v, int c) {
    return (c == 0) ? v.x : (c == 1) ? v.y : (c == 2) ? v.z : v.w;
}

__global__ __launch_bounds__(256)
void qkv_kernel(const float* __restrict__ X,
                const float* __restrict__ WQ, const float* __restrict__ bQ,
                const float* __restrict__ WK, const float* __restrict__ bK,
                const float* __restrict__ WV, const float* __restrict__ bV)
{
    const float* W; const float* bias;
    if (blockIdx.z == 0)      { W = WQ; bias = bQ; }
    else if (blockIdx.z == 1) { W = WK; bias = bK; }
    else                      { W = WV; bias = bV; }

    __shared__ float Xs[64][68];
    __shared__ float Ws[64][64];

    const int tid = threadIdx.x;
    const int ty = tid >> 4, tx = tid & 15;
    const int m0 = blockIdx.x * 64, n0 = blockIdx.y * 64;

    float acc[4][4] = {};

    for (int k0 = 0; k0 < 256; k0 += 64) {
        #pragma unroll
        for (int i = 0; i < 16; i++) {
            int idx = tid + i * 256;
            int r = idx >> 6, c = idx & 63;
            Xs[r][c] = X[(m0 + r) * XLD + (k0 + c)];
        }
        #pragma unroll
        for (int i = 0; i < 4; i++) {
            int idx = tid + i * 256;
            int r = idx >> 4, c4 = (idx & 15) << 2;
            *(float4*)&Ws[r][c4] = *(const float4*)&W[(k0 + r) * 256 + (n0 + c4)];
        }
        __syncthreads();
        #pragma unroll 4
        for (int k = 0; k < 64; k += 4) {
            float4 xv[4];
            #pragma unroll
            for (int i = 0; i < 4; i++) xv[i] = *(const float4*)&Xs[ty * 4 + i][k];
            #pragma unroll
            for (int kk = 0; kk < 4; kk++) {
                float wv[4];
                #pragma unroll
                for (int j = 0; j < 4; j++) wv[j] = Ws[k + kk][tx + 16 * j];
                #pragma unroll
                for (int i = 0; i < 4; i++) {
                    float xs = f4get(xv[i], kk);
                    #pragma unroll
                    for (int j = 0; j < 4; j++) acc[i][j] += xs * wv[j];
                }
            }
        }
        __syncthreads();
    }

    if (blockIdx.z == 2) {
        #pragma unroll
        for (int j = 0; j < 4; j++) {
            int n = n0 + tx + 16 * j;
            float bv = bias[n];
            #pragma unroll
            for (int i = 0; i < 4; i++)
                g_Vt[(size_t)n * NT + (m0 + ty * 4 + i)] = __float2bfloat16_rn(acc[i][j] + bv);
        }
    } else {
        __nv_bfloat16* C = (blockIdx.z == 0) ? g_Qb : g_Kb;
        #pragma unroll
        for (int j = 0; j < 4; j++) {
            int n = n0 + tx + 16 * j;
            float bv = bias[n];
            #pragma unroll
            for (int i = 0; i < 4; i++)
                C[(size_t)(m0 + ty * 4 + i) * 256 + n] = __float2bfloat16_rn(acc[i][j] + bv);
        }
    }
}

__global__ void pos_kernel(const float* __restrict__ X)
{
    int i = blockIdx.x * 256 + threadIdx.x;
    float x = X[(size_t)i * XLD + 256];
    float y = X[(size_t)i * XLD + 257];
    float z = X[(size_t)i * XLD + 258];
    g_pos4[i] = make_float4(x, y, z, x * x + y * y + z * z);
}

// ---------------- tile loaders (cp.async, SW128-swizzled, 512 threads) ----------------
__device__ __forceinline__ void load_k(uint32_t sb, int tid, int j0, int buf) {
    uint32_t kb = sb + SM_K + (uint32_t)buf * 32768u;
    #pragma unroll
    for (int i = 0; i < 4; i++) {
        int e = i * 512 + tid;               // 0..2047
        int key = e >> 5, q = e & 31;
        int fb = q >> 3, f8 = q & 7;
        uint32_t off = (uint32_t)(fb * 8192 + SWZ(key * 128 + f8 * 16));
        cp16(kb + off, (const char*)g_Kb + (((size_t)(j0 + key)) * 256 + fb * 64 + f8 * 8) * 2);
    }
}
__device__ __forceinline__ void load_v(uint32_t sb, int tid, int j0, int buf) {
    uint32_t vb = sb + SM_V + (uint32_t)buf * 32768u;
    #pragma unroll
    for (int i = 0; i < 4; i++) {
        int e = i * 512 + tid;
        int dim = e >> 3, q = e & 7;
        uint32_t off = (uint32_t)SWZ(dim * 128 + q * 16);
        cp16(vb + off, (const char*)g_Vt + (((size_t)dim) * NT + j0 + q * 8) * 2);
    }
}
__device__ __forceinline__ void load_pos(uint32_t sb, int tid, int j0, int buf) {
    if (tid < 64) cp16(sb + SM_POS + (uint32_t)buf * 1024u + tid * 16u, &g_pos4[j0 + tid]);
}

__device__ __forceinline__ float softel(float s, float4 q, float4 k, float& rmx) {
    float dot = fmaf(q.z, k.z, fmaf(q.y, k.y, q.x * k.x));
    float d2 = fmaxf(fmaf(-2.f, dot, q.w + k.w), 0.f);
    float x = s * 0.0625f * __expf(-0.5f * d2);
    rmx = fmaxf(rmx, x);
    return __expf(x);
}

// ---------------------------------------------------------------------------
// HMMA flash attention, 512 threads / 16 warps.
// warp = (rb = w&7 -> rows 16rb..+15, db = w>>3).
// S: warp computes rows x keys[db*32..+31]; P exchanged via smem;
// PV: warp computes rows x dims[db*128..+127].  O = 64 regs/thread.
// Unshifted exp: p=exp(x), m scalar max, O never rescaled; merge divides.
// ---------------------------------------------------------------------------
__global__ __launch_bounds__(512, 1)
void attn_kernel()
{
    extern __shared__ char smem[];
    const uint32_t sb = smem_u32(smem);
    const int tid = threadIdx.x;
    const int w = tid >> 5, l = tid & 31;
    const int rb = w & 7, db = w >> 3;
    const int g = l >> 2, t = l & 3;
    const int qb = blockIdx.x >> 1, half = blockIdx.x & 1;
    const int m0 = qb * 128, j0b = half * 4096;

    // ---- Q -> smem (once), K/V/pos tile 0 ----
    #pragma unroll
    for (int i = 0; i < 8; i++) {
        int e = i * 512 + tid;               // 0..4095
        int row = e >> 5, q = e & 31;
        int fb = q >> 3, f8 = q & 7;
        uint32_t off = (uint32_t)(fb * 16384 + SWZ(row * 128 + f8 * 16));
        cp16(sb + SM_Q + off, (const char*)g_Qb + (((size_t)(m0 + row)) * 256 + fb * 64 + f8 * 8) * 2);
    }
    load_k(sb, tid, j0b, 0);
    load_v(sb, tid, j0b, 0);
    load_pos(sb, tid, j0b, 0);
    CP_COMMIT();

    const float4 qpa = g_pos4[m0 + 16 * rb + g];
    const float4 qpb = g_pos4[m0 + 16 * rb + g + 8];

    float O[16][4];                          // rows (g,g+8) x dims db*128 + 8*on + {0,1}
    #pragma unroll
    for (int n = 0; n < 16; n++) { O[n][0] = O[n][1] = O[n][2] = O[n][3] = 0.f; }
    float rmax0 = -1e30f, rmax1 = -1e30f, rsum0 = 0.f, rsum1 = 0.f;

    // ldmatrix lane address components
    const int lrow16 = l & 15;
    const int lkh    = l >> 4;
    const int lr8    = (l & 7) + (l >> 4) * 8;
    const int lbh    = (l >> 3) & 1;

    for (int tt = 0; tt < NTILES; tt++) {
        const int buf = tt & 1;
        if (tt < NTILES - 1) {
            load_k(sb, tid, j0b + (tt + 1) * 64, (tt + 1) & 1);
            load_v(sb, tid, j0b + (tt + 1) * 64, (tt + 1) & 1);
            load_pos(sb, tid, j0b + (tt + 1) * 64, (tt + 1) & 1);
            CP_COMMIT();
            CP_WAIT1();
        } else {
            CP_WAIT0();
        }
        __syncthreads();

        // ---- S = Q K^T : rows 16rb..+15  x  keys db*32..+31, depth 256 ----
        float S[4][4];
        #pragma unroll
        for (int n = 0; n < 4; n++) { S[n][0] = S[n][1] = S[n][2] = S[n][3] = 0.f; }
        const uint32_t kbase = sb + SM_K + (uint32_t)buf * 32768u;

        #pragma unroll 8
        for (int ks = 0; ks < 16; ks++) {
            const int fb = ks >> 2, kc = (ks & 3) * 2;
            uint32_t a0, a1, a2, a3;
            ldsm4(sb + SM_Q + fb * 16384 + SWZ((16 * rb + lrow16) * 128 + (kc + lkh) * 16),
                  a0, a1, a2, a3);
            #pragma unroll
            for (int jj = 0; jj < 2; jj++) {
                uint32_t b0, b1, b2, b3;
                ldsm4(kbase + fb * 8192 + SWZ((db * 32 + 16 * jj + lr8) * 128 + (kc + lbh) * 16),
                      b0, b1, b2, b3);
                mma_bf16(S[2*jj][0], S[2*jj][1], S[2*jj][2], S[2*jj][3], a0, a1, a2, a3, b0, b1);
                mma_bf16(S[2*jj+1][0], S[2*jj+1][1], S[2*jj+1][2], S[2*jj+1][3], a0, a1, a2, a3, b2, b3);
            }
        }

        // ---- softmax + decay -> P smem (bf16) ----
        const char* posb = smem + SM_POS + buf * 1024;
        #pragma unroll
        for (int nt = 0; nt < 4; nt++) {
            int c0 = db * 32 + 8 * nt + 2 * t;           // key col within tile
            float4 k0 = *(const float4*)(posb + c0 * 16);
            float4 k1 = *(const float4*)(posb + c0 * 16 + 16);
            float p00 = softel(S[nt][0], qpa, k0, rmax0);
            float p01 = softel(S[nt][1], qpa, k1, rmax0);
            float p10 = softel(S[nt][2], qpb, k0, rmax1);
            float p11 = softel(S[nt][3], qpb, k1, rmax1);
            rsum0 += p00 + p01;
            rsum1 += p10 + p11;
            __nv_bfloat162 h0 = __floats2bfloat162_rn(p00, p01);
            __nv_bfloat162 h1 = __floats2bfloat162_rn(p10, p11);
            *(uint32_t*)(smem + SM_P + SWZ((16 * rb + g) * 128 + c0 * 2)) = *(uint32_t*)&h0;
            *(uint32_t*)(smem + SM_P + SWZ((16 * rb + g + 8) * 128 + c0 * 2)) = *(uint32_t*)&h1;
        }
        __syncthreads();   // P complete

        // ---- O += P V : rows 16rb..+15 x dims db*128..+127, k = 64 keys ----
        const uint32_t vbase = sb + SM_V + (uint32_t)buf * 32768u;
        #pragma unroll
        for (int kp = 0; kp < 4; kp++) {
            uint32_t a0, a1, a2, a3;
            ldsm4(sb + SM_P + SWZ((16 * rb + lrow16) * 128 + (2 * kp + lkh) * 16),
                  a0, a1, a2, a3);
            #pragma unroll
            for (int dd = 0; dd < 8; dd++) {
                uint32_t b0, b1, b2, b3;
                ldsm4(vbase + SWZ((db * 128 + 16 * dd + lr8) * 128 + (2 * kp + lbh) * 16),
                      b0, b1, b2, b3);
                mma_bf16(O[2*dd][0], O[2*dd][1], O[2*dd][2], O[2*dd][3], a0, a1, a2, a3, b0, b1);
                mma_bf16(O[2*dd+1][0], O[2*dd+1][1], O[2*dd+1][2], O[2*dd+1][3], a0, a1, a2, a3, b2, b3);
            }
        }
        __syncthreads();   // all warps done with K/V buf and P before overwrite
    }

    // ---- row stats: quad-reduce, then cross-db via smem ----
    #pragma unroll
    for (int off = 1; off <= 2; off <<= 1) {
        rmax0 = fmaxf(rmax0, __shfl_xor_sync(0xffffffffu, rmax0, off));
        rmax1 = fmaxf(rmax1, __shfl_xor_sync(0xffffffffu, rmax1, off));
        rsum0 += __shfl_xor_sync(0xffffffffu, rsum0, off);
        rsum1 += __shfl_xor_sync(0xffffffffu, rsum1, off);
    }
    float* red_m = (float*)(smem + SM_RED);          // [2][128]
    float* red_s = (float*)(smem + SM_RED + 1024);   // [2][128]
    if (t == 0) {
        red_m[db * 128 + 16 * rb + g]     = rmax0;
        red_m[db * 128 + 16 * rb + g + 8] = rmax1;
        red_s[db * 128 + 16 * rb + g]     = rsum0;
        red_s[db * 128 + 16 * rb + g + 8] = rsum1;
    }
    __syncthreads();
    if (tid < 128) {
        g_mpart[half * NT + m0 + tid] = fmaxf(red_m[tid], red_m[128 + tid]);
        g_spart[half * NT + m0 + tid] = red_s[tid] + red_s[128 + tid];
    }

    // ---- O writeback (fp32 partials) ----
    float* ob = &g_Opart[(size_t)half * NT * 256];
    const int row0 = m0 + 16 * rb + g;
    #pragma unroll
    for (int on = 0; on < 16; on++) {
        int col = db * 128 + 8 * on + 2 * t;
        *(float2*)&ob[(size_t)row0 * 256 + col]       = make_float2(O[on][0], O[on][1]);
        *(float2*)&ob[(size_t)(row0 + 8) * 256 + col] = make_float2(O[on][2], O[on][3]);
    }
}

// ---------------------------------------------------------------------------
// merge: H = (O0+O1)/(exp(max(m0,m1)) + s0 + s1) + Xf
// ---------------------------------------------------------------------------
__global__ __launch_bounds__(256)
void merge_kernel(const float* __restrict__ X, float* __restrict__ out)
{
    int r = blockIdx.x * 4 + (threadIdx.x >> 6);
    int c = (threadIdx.x & 63) * 4;
    float m = fmaxf(g_mpart[r], g_mpart[NT + r]);
    float d = 1.f / (__expf(m) + g_spart[r] + g_spart[NT + r]);
    float4 o0 = *(const float4*)&g_Opart[(size_t)r * 256 + c];
    float4 o1 = *(const float4*)&g_Opart[(size_t)NT * 256 + (size_t)r * 256 + c];
    const float* xr = &X[(size_t)r * XLD + c];
    float4 o;
    o.x = (o0.x + o1.x) * d + xr[0];
    o.y = (o0.y + o1.y) * d + xr[1];
    o.z = (o0.z + o1.z) * d + xr[2];
    o.w = (o0.w + o1.w) * d + xr[3];
    *(float4*)&out[(size_t)r * 256 + c] = o;
}

extern "C" void kernel_launch(void* const* d_in, const int* in_sizes, int n_in,
                              void* d_out, int out_size)
{
    const float* X  = (const float*)d_in[0];
    const float* WQ = (const float*)d_in[1];
    const float* bQ = (const float*)d_in[2];
    const float* WK = (const float*)d_in[3];
    const float* bK = (const float*)d_in[4];
    const float* WV = (const float*)d_in[5];
    const float* bV = (const float*)d_in[6];
    float* out = (float*)d_out;

    cudaFuncSetAttribute(attn_kernel, cudaFuncAttributeMaxDynamicSharedMemorySize, ATTN_SMEM);

    pos_kernel<<<NT / 256, 256>>>(X);
    dim3 g1(NT / 64, 4, 3);
    qkv_kernel<<<g1, 256>>>(X, WQ, bQ, WK, bK, WV, bV);
    attn_kernel<<<128, 512, ATTN_SMEM>>>();
    merge_kernel<<<NT / 4, 256>>>(X, out);
}

// round 13
// speedup vs baseline: 5.5671x; 1.0031x over previous
#include <cuda_runtime.h>
#include <cuda_bf16.h>
#include <cstdint>
#include <cstddef>

#define NT     8192
#define XLD    259
#define NTILES 64           // 4096 keys per CTA half / 64 per tile

// ---------------- device globals ----------------
__device__ __nv_bfloat16 g_Qb[NT * 256];
__device__ __nv_bfloat16 g_Kb[NT * 256];
__device__ __nv_bfloat16 g_Vt[256 * NT];     // V transposed: [dim][token]
__device__ float4        g_pos4[NT];         // px,py,pz,|p|^2
__device__ float         g_Opart[2 * NT * 256];
__device__ float         g_spart[2 * NT];
__device__ float         g_mpart[2 * NT];

// ---------------- PTX helpers (base ISA only) ----------------
__device__ __forceinline__ uint32_t smem_u32(const void* p) {
    uint32_t a;
    asm("{ .reg .u64 t; cvta.to.shared.u64 t, %1; cvt.u32.u64 %0, t; }" : "=r"(a) : "l"(p));
    return a;
}
#define CP_COMMIT() asm volatile("cp.async.commit_group;" ::: "memory")
#define CP_WAIT0()  asm volatile("cp.async.wait_group 0;" ::: "memory")
__device__ __forceinline__ void cp16(uint32_t dst, const void* src) {
    asm volatile("cp.async.cg.shared.global [%0], [%1], 16;" :: "r"(dst), "l"(src));
}
__device__ __forceinline__ void ldsm4(uint32_t addr, uint32_t& r0, uint32_t& r1, uint32_t& r2, uint32_t& r3) {
    asm volatile("ldmatrix.sync.aligned.m8n8.x4.shared.b16 {%0,%1,%2,%3}, [%4];"
        : "=r"(r0), "=r"(r1), "=r"(r2), "=r"(r3) : "r"(addr));
}
__device__ __forceinline__ void mma_bf16(float& c0, float& c1, float& c2, float& c3,
                                         uint32_t a0, uint32_t a1, uint32_t a2, uint32_t a3,
                                         uint32_t b0, uint32_t b1) {
    asm volatile("mma.sync.aligned.m16n8k16.row.col.f32.bf16.bf16.f32 "
        "{%0,%1,%2,%3}, {%4,%5,%6,%7}, {%8,%9}, {%0,%1,%2,%3};"
        : "+f"(c0), "+f"(c1), "+f"(c2), "+f"(c3)
        : "r"(a0), "r"(a1), "r"(a2), "r"(a3), "r"(b0), "r"(b1));
}
#define SWZ(x) ((x) ^ (((x) >> 3) & 0x70))

// ---------------- SMEM layout (attn) ----------------
#define SM_POS  0          // 2 x 1024
#define SM_P    2048       // 16384  (128 rows x 64 keys bf16, 128B rows)
#define SM_Q    18432      // 65536  (4 fb-blocks x 128 rows x 128B)
#define SM_K    83968      // 2 x 32768
#define SM_V    149504     // 2 x 32768
#define SM_RED  215040     // 2048: red_m[2][128], red_s[2][128]
#define ATTN_SMEM 217088

// ---------------------------------------------------------------------------
// QKV GEMM (SIMT fp32) -> bf16; V stored transposed.
// ---------------------------------------------------------------------------
__device__ __forceinline__ float f4get(float4 v, int c) {
    return (c == 0) ? v.x : (c == 1) ? v.y : (c == 2) ? v.z : v.w;
}

__global__ __launch_bounds__(256)
void qkv_kernel(const float* __restrict__ X,
                const float* __restrict__ WQ, const float* __restrict__ bQ,
                const float* __restrict__ WK, const float* __restrict__ bK,
                const float* __restrict__ WV, const float* __restrict__ bV)
{
    const float* W; const float* bias;
    if (blockIdx.z == 0)      { W = WQ; bias = bQ; }
    else if (blockIdx.z == 1) { W = WK; bias = bK; }
    else                      { W = WV; bias = bV; }

    __shared__ float Xs[64][68];
    __shared__ float Ws[64][64];

    const int tid = threadIdx.x;
    const int ty = tid >> 4, tx = tid & 15;
    const int m0 = blockIdx.x * 64, n0 = blockIdx.y * 64;

    float acc[4][4] = {};

    for (int k0 = 0; k0 < 256; k0 += 64) {
        #pragma unroll
        for (int i = 0; i < 16; i++) {
            int idx = tid + i * 256;
            int r = idx >> 6, c = idx & 63;
            Xs[r][c] = X[(m0 + r) * XLD + (k0 + c)];
        }
        #pragma unroll
        for (int i = 0; i < 4; i++) {
            int idx = tid + i * 256;
            int r = idx >> 4, c4 = (idx & 15) << 2;
            *(float4*)&Ws[r][c4] = *(const float4*)&W[(k0 + r) * 256 + (n0 + c4)];
        }
        __syncthreads();
        #pragma unroll 4
        for (int k = 0; k < 64; k += 4) {
            float4 xv[4];
            #pragma unroll
            for (int i = 0; i < 4; i++) xv[i] = *(const float4*)&Xs[ty * 4 + i][k];
            #pragma unroll
            for (int kk = 0; kk < 4; kk++) {
                float wv[4];
                #pragma unroll
                for (int j = 0; j < 4; j++) wv[j] = Ws[k + kk][tx + 16 * j];
                #pragma unroll
                for (int i = 0; i < 4; i++) {
                    float xs = f4get(xv[i], kk);
                    #pragma unroll
                    for (int j = 0; j < 4; j++) acc[i][j] += xs * wv[j];
                }
            }
        }
        __syncthreads();
    }

    if (blockIdx.z == 2) {
        #pragma unroll
        for (int j = 0; j < 4; j++) {
            int n = n0 + tx + 16 * j;
            float bv = bias[n];
            #pragma unroll
            for (int i = 0; i < 4; i++)
                g_Vt[(size_t)n * NT + (m0 + ty * 4 + i)] = __float2bfloat16_rn(acc[i][j] + bv);
        }
    } else {
        __nv_bfloat16* C = (blockIdx.z == 0) ? g_Qb : g_Kb;
        #pragma unroll
        for (int j = 0; j < 4; j++) {
            int n = n0 + tx + 16 * j;
            float bv = bias[n];
            #pragma unroll
            for (int i = 0; i < 4; i++)
                C[(size_t)(m0 + ty * 4 + i) * 256 + n] = __float2bfloat16_rn(acc[i][j] + bv);
        }
    }
}

__global__ void pos_kernel(const float* __restrict__ X)
{
    int i = blockIdx.x * 256 + threadIdx.x;
    float x = X[(size_t)i * XLD + 256];
    float y = X[(size_t)i * XLD + 257];
    float z = X[(size_t)i * XLD + 258];
    g_pos4[i] = make_float4(x, y, z, x * x + y * y + z * z);
}

// ---------------- tile loaders (cp.async, SW128-swizzled, 512 threads) ----------------
__device__ __forceinline__ void load_k(uint32_t sb, int tid, int j0, int buf) {
    uint32_t kb = sb + SM_K + (uint32_t)buf * 32768u;
    #pragma unroll
    for (int i = 0; i < 4; i++) {
        int e = i * 512 + tid;               // 0..2047
        int key = e >> 5, q = e & 31;
        int fb = q >> 3, f8 = q & 7;
        uint32_t off = (uint32_t)(fb * 8192 + SWZ(key * 128 + f8 * 16));
        cp16(kb + off, (const char*)g_Kb + (((size_t)(j0 + key)) * 256 + fb * 64 + f8 * 8) * 2);
    }
}
__device__ __forceinline__ void load_v(uint32_t sb, int tid, int j0, int buf) {
    uint32_t vb = sb + SM_V + (uint32_t)buf * 32768u;
    #pragma unroll
    for (int i = 0; i < 4; i++) {
        int e = i * 512 + tid;
        int dim = e >> 3, q = e & 7;
        uint32_t off = (uint32_t)SWZ(dim * 128 + q * 16);
        cp16(vb + off, (const char*)g_Vt + (((size_t)dim) * NT + j0 + q * 8) * 2);
    }
}
__device__ __forceinline__ void load_pos(uint32_t sb, int tid, int j0, int buf) {
    if (tid < 64) cp16(sb + SM_POS + (uint32_t)buf * 1024u + tid * 16u, &g_pos4[j0 + tid]);
}

__device__ __forceinline__ float softel(float s, float4 q, float4 k, float& rmx) {
    float dot = fmaf(q.z, k.z, fmaf(q.y, k.y, q.x * k.x));
    float d2 = fmaxf(fmaf(-2.f, dot, q.w + k.w), 0.f);
    float x = s * 0.0625f * __expf(-0.5f * d2);
    rmx = fmaxf(rmx, x);
    return __expf(x);
}

// ---------------------------------------------------------------------------
// HMMA flash attention, 512 threads / 16 warps, 2 barriers per tile.
// S phase : warp = (rb = w&7 -> 16 rows, db = w>>3 -> 32 keys)
// PV phase: warp = (rb2 = w&3 -> 32 rows, db2 = w>>2 -> 64 dims)  [4x4 split]
// Unshifted exp: p=exp(x), m scalar max, O never rescaled; merge divides.
// ---------------------------------------------------------------------------
__global__ __launch_bounds__(512, 1)
void attn_kernel()
{
    extern __shared__ char smem[];
    const uint32_t sb = smem_u32(smem);
    const int tid = threadIdx.x;
    const int w = tid >> 5, l = tid & 31;
    const int rb = w & 7, db = w >> 3;        // S-phase mapping
    const int rb2 = w & 3, db2 = w >> 2;      // PV-phase mapping
    const int g = l >> 2, t = l & 3;
    const int qb = blockIdx.x >> 1, half = blockIdx.x & 1;
    const int m0 = qb * 128, j0b = half * 4096;

    // ---- Q -> smem (once), K/V/pos tile 0 ----
    #pragma unroll
    for (int i = 0; i < 8; i++) {
        int e = i * 512 + tid;               // 0..4095
        int row = e >> 5, q = e & 31;
        int fb = q >> 3, f8 = q & 7;
        uint32_t off = (uint32_t)(fb * 16384 + SWZ(row * 128 + f8 * 16));
        cp16(sb + SM_Q + off, (const char*)g_Qb + (((size_t)(m0 + row)) * 256 + fb * 64 + f8 * 8) * 2);
    }
    load_k(sb, tid, j0b, 0);
    load_v(sb, tid, j0b, 0);
    load_pos(sb, tid, j0b, 0);
    CP_COMMIT();

    const float4 qpa = g_pos4[m0 + 16 * rb + g];
    const float4 qpb = g_pos4[m0 + 16 * rb + g + 8];

    float O[16][4];                           // [mr*8+on][4]: rows 32rb2+16mr+{g,g+8}, col 64db2+8on+2t
    #pragma unroll
    for (int n = 0; n < 16; n++) { O[n][0] = O[n][1] = O[n][2] = O[n][3] = 0.f; }
    float rmax0 = -1e30f, rmax1 = -1e30f, rsum0 = 0.f, rsum1 = 0.f;

    // ldmatrix lane address components
    const int lrow16 = l & 15;
    const int lkh    = l >> 4;
    const int lr8    = (l & 7) + (l >> 4) * 8;
    const int lbh    = (l >> 3) & 1;

    for (int tt = 0; tt < NTILES; tt++) {
        const int buf = tt & 1;
        // KV(tt) complete for this thread; barrier makes it visible to all AND
        // guarantees every warp finished PV(tt-1) (so prefetch below is race-free).
        CP_WAIT0();
        __syncthreads();
        if (tt < NTILES - 1) {
            load_k(sb, tid, j0b + (tt + 1) * 64, (tt + 1) & 1);
            load_v(sb, tid, j0b + (tt + 1) * 64, (tt + 1) & 1);
            load_pos(sb, tid, j0b + (tt + 1) * 64, (tt + 1) & 1);
            CP_COMMIT();
        }

        // ---- S = Q K^T : rows 16rb..+15  x  keys db*32..+31, depth 256 ----
        float S[4][4];
        #pragma unroll
        for (int n = 0; n < 4; n++) { S[n][0] = S[n][1] = S[n][2] = S[n][3] = 0.f; }
        const uint32_t kbase = sb + SM_K + (uint32_t)buf * 32768u;

        #pragma unroll 8
        for (int ks = 0; ks < 16; ks++) {
            const int fb = ks >> 2, kc = (ks & 3) * 2;
            uint32_t a0, a1, a2, a3;
            ldsm4(sb + SM_Q + fb * 16384 + SWZ((16 * rb + lrow16) * 128 + (kc + lkh) * 16),
                  a0, a1, a2, a3);
            #pragma unroll
            for (int jj = 0; jj < 2; jj++) {
                uint32_t b0, b1, b2, b3;
                ldsm4(kbase + fb * 8192 + SWZ((db * 32 + 16 * jj + lr8) * 128 + (kc + lbh) * 16),
                      b0, b1, b2, b3);
                mma_bf16(S[2*jj][0], S[2*jj][1], S[2*jj][2], S[2*jj][3], a0, a1, a2, a3, b0, b1);
                mma_bf16(S[2*jj+1][0], S[2*jj+1][1], S[2*jj+1][2], S[2*jj+1][3], a0, a1, a2, a3, b2, b3);
            }
        }

        // ---- softmax + decay -> P smem (bf16) ----
        const char* posb = smem + SM_POS + buf * 1024;
        #pragma unroll
        for (int nt = 0; nt < 4; nt++) {
            int c0 = db * 32 + 8 * nt + 2 * t;
            float4 k0 = *(const float4*)(posb + c0 * 16);
            float4 k1 = *(const float4*)(posb + c0 * 16 + 16);
            float p00 = softel(S[nt][0], qpa, k0, rmax0);
            float p01 = softel(S[nt][1], qpa, k1, rmax0);
            float p10 = softel(S[nt][2], qpb, k0, rmax1);
            float p11 = softel(S[nt][3], qpb, k1, rmax1);
            rsum0 += p00 + p01;
            rsum1 += p10 + p11;
            __nv_bfloat162 h0 = __floats2bfloat162_rn(p00, p01);
            __nv_bfloat162 h1 = __floats2bfloat162_rn(p10, p11);
            *(uint32_t*)(smem + SM_P + SWZ((16 * rb + g) * 128 + c0 * 2)) = *(uint32_t*)&h0;
            *(uint32_t*)(smem + SM_P + SWZ((16 * rb + g + 8) * 128 + c0 * 2)) = *(uint32_t*)&h1;
        }
        __syncthreads();   // P complete

        // ---- O += P V : rows 32rb2..+31 x dims 64db2..+63, k = 64 keys ----
        const uint32_t vbase = sb + SM_V + (uint32_t)buf * 32768u;
        #pragma unroll
        for (int kp = 0; kp < 4; kp++) {
            uint32_t pa[2][4];
            #pragma unroll
            for (int mr = 0; mr < 2; mr++)
                ldsm4(sb + SM_P + SWZ((32 * rb2 + 16 * mr + lrow16) * 128 + (2 * kp + lkh) * 16),
                      pa[mr][0], pa[mr][1], pa[mr][2], pa[mr][3]);
            #pragma unroll
            for (int dd = 0; dd < 4; dd++) {
                uint32_t b0, b1, b2, b3;
                ldsm4(vbase + SWZ((64 * db2 + 16 * dd + lr8) * 128 + (2 * kp + lbh) * 16),
                      b0, b1, b2, b3);
                #pragma unroll
                for (int mr = 0; mr < 2; mr++) {
                    mma_bf16(O[mr*8+2*dd][0], O[mr*8+2*dd][1], O[mr*8+2*dd][2], O[mr*8+2*dd][3],
                             pa[mr][0], pa[mr][1], pa[mr][2], pa[mr][3], b0, b1);
                    mma_bf16(O[mr*8+2*dd+1][0], O[mr*8+2*dd+1][1], O[mr*8+2*dd+1][2], O[mr*8+2*dd+1][3],
                             pa[mr][0], pa[mr][1], pa[mr][2], pa[mr][3], b2, b3);
                }
            }
        }
        // no barrier here: the loop-top sync covers P/KV reuse
    }

    // ---- row stats: quad-reduce, then cross-db via smem ----
    #pragma unroll
    for (int off = 1; off <= 2; off <<= 1) {
        rmax0 = fmaxf(rmax0, __shfl_xor_sync(0xffffffffu, rmax0, off));
        rmax1 = fmaxf(rmax1, __shfl_xor_sync(0xffffffffu, rmax1, off));
        rsum0 += __shfl_xor_sync(0xffffffffu, rsum0, off);
        rsum1 += __shfl_xor_sync(0xffffffffu, rsum1, off);
    }
    float* red_m = (float*)(smem + SM_RED);          // [2][128]
    float* red_s = (float*)(smem + SM_RED + 1024);   // [2][128]
    __syncthreads();   // all PV reads of P done before red arrays alias... (distinct region; barrier orders stats)
    if (t == 0) {
        red_m[db * 128 + 16 * rb + g]     = rmax0;
        red_m[db * 128 + 16 * rb + g + 8] = rmax1;
        red_s[db * 128 + 16 * rb + g]     = rsum0;
        red_s[db * 128 + 16 * rb + g + 8] = rsum1;
    }
    __syncthreads();
    if (tid < 128) {
        g_mpart[half * NT + m0 + tid] = fmaxf(red_m[tid], red_m[128 + tid]);
        g_spart[half * NT + m0 + tid] = red_s[tid] + red_s[128 + tid];
    }

    // ---- O writeback (fp32 partials) ----
    float* ob = &g_Opart[(size_t)half * NT * 256];
    #pragma unroll
    for (int mr = 0; mr < 2; mr++) {
        int row0 = m0 + 32 * rb2 + 16 * mr + g;
        #pragma unroll
        for (int on = 0; on < 8; on++) {
            int col = 64 * db2 + 8 * on + 2 * t;
            *(float2*)&ob[(size_t)row0 * 256 + col]       = make_float2(O[mr*8+on][0], O[mr*8+on][1]);
            *(float2*)&ob[(size_t)(row0 + 8) * 256 + col] = make_float2(O[mr*8+on][2], O[mr*8+on][3]);
        }
    }
}

// ---------------------------------------------------------------------------
// merge: H = (O0+O1)/(exp(max(m0,m1)) + s0 + s1) + Xf
// ---------------------------------------------------------------------------
__global__ __launch_bounds__(256)
void merge_kernel(const float* __restrict__ X, float* __restrict__ out)
{
    int r = blockIdx.x * 4 + (threadIdx.x >> 6);
    int c = (threadIdx.x & 63) * 4;
    float m = fmaxf(g_mpart[r], g_mpart[NT + r]);
    float d = 1.f / (__expf(m) + g_spart[r] + g_spart[NT + r]);
    float4 o0 = *(const float4*)&g_Opart[(size_t)r * 256 + c];
    float4 o1 = *(const float4*)&g_Opart[(size_t)NT * 256 + (size_t)r * 256 + c];
    const float* xr = &X[(size_t)r * XLD + c];
    float4 o;
    o.x = (o0.x + o1.x) * d + xr[0];
    o.y = (o0.y + o1.y) * d + xr[1];
    o.z = (o0.z + o1.z) * d + xr[2];
    o.w = (o0.w + o1.w) * d + xr[3];
    *(float4*)&out[(size_t)r * 256 + c] = o;
}

extern "C" void kernel_launch(void* const* d_in, const int* in_sizes, int n_in,
                              void* d_out, int out_size)
{
    const float* X  = (const float*)d_in[0];
    const float* WQ = (const float*)d_in[1];
    const float* bQ = (const float*)d_in[2];
    const float* WK = (const float*)d_in[3];
    const float* bK = (const float*)d_in[4];
    const float* WV = (const float*)d_in[5];
    const float* bV = (const float*)d_in[6];
    float* out = (float*)d_out;

    cudaFuncSetAttribute(attn_kernel, cudaFuncAttributeMaxDynamicSharedMemorySize, ATTN_SMEM);

    pos_kernel<<<NT / 256, 256>>>(X);
    dim3 g1(NT / 64, 4, 3);
    qkv_kernel<<<g1, 256>>>(X, WQ, bQ, WK, bK, WV, bV);
    attn_kernel<<<128, 512, ATTN_SMEM>>>();
    merge_kernel<<<NT / 4, 256>>>(X, out);
}